// round 10
// baseline (speedup 1.0000x reference)
#include <cuda_runtime.h>

#define NN 100000
#define EE 3200000
#define E4 (EE / 4)

// Scratch (__device__ globals; zero-initialized at module load).
// INVARIANT: g_deg, g_sab, g_t are zero at entry to kernel_launch; k_final
// re-zeroes them after use so the invariant holds for the next call.
__device__ float  g_deg[NN];
__device__ float  g_dinv[NN];
__device__ float2 g_ab[NN];    // (dinv*x0, dinv*x1) per node
__device__ float2 g_sab[NN];   // layer-1 accumulators
__device__ float  g_q[NN];
__device__ float  g_t[NN];

__device__ __forceinline__ void red_add_v2(float2* addr, float a, float b) {
    asm volatile("red.global.add.v2.f32 [%0], {%1, %2};"
                 :: "l"(addr), "f"(a), "f"(b) : "memory");
}

// K1: degree count over edge destinations (col), int4, 2 per thread
__global__ void __launch_bounds__(256) k_deg(const int4* __restrict__ col4, int e4) {
    int i = (blockIdx.x * blockDim.x + threadIdx.x) * 2;
    #pragma unroll
    for (int u = 0; u < 2; u++) {
        int idx = i + u;
        if (idx < e4) {
            int4 c = __ldg(&col4[idx]);
            atomicAdd(&g_deg[c.x], 1.0f);
            atomicAdd(&g_deg[c.y], 1.0f);
            atomicAdd(&g_deg[c.z], 1.0f);
            atomicAdd(&g_deg[c.w], 1.0f);
        }
    }
}

// K2: per-node dinv = rsqrt(deg + 1 self-loop); (a,b) = dinv * x
__global__ void __launch_bounds__(256) k_node1(const float* __restrict__ x, int n) {
    int i = blockIdx.x * blockDim.x + threadIdx.x;
    cudaGridDependencySynchronize();   // wait for k_deg results
    if (i < n) {
        float dinv = rsqrtf(g_deg[i] + 1.0f);
        float2 xi = ((const float2*)x)[i];
        g_dinv[i] = dinv;
        g_ab[i] = make_float2(dinv * xi.x, dinv * xi.y);
    }
}

// K3: layer-1 edge scatter — one 64b gather + one 64b vector RED per edge
__global__ void __launch_bounds__(256) k_scatter1(const int4* __restrict__ row4,
                                                  const int4* __restrict__ col4, int e4) {
    int i = (blockIdx.x * blockDim.x + threadIdx.x) * 2;
    cudaGridDependencySynchronize();   // wait for k_node1 (g_ab)
    #pragma unroll
    for (int u = 0; u < 2; u++) {
        int idx = i + u;
        if (idx < e4) {
            int4 r = __ldg(&row4[idx]);
            int4 c = __ldg(&col4[idx]);
            float2 v0 = __ldg(&g_ab[r.x]);
            float2 v1 = __ldg(&g_ab[r.y]);
            float2 v2 = __ldg(&g_ab[r.z]);
            float2 v3 = __ldg(&g_ab[r.w]);
            red_add_v2(&g_sab[c.x], v0.x, v0.y);
            red_add_v2(&g_sab[c.y], v1.x, v1.y);
            red_add_v2(&g_sab[c.z], v2.x, v2.y);
            red_add_v2(&g_sab[c.w], v3.x, v3.y);
        }
    }
}

// K4: per-node MLP — reconstruct h1 (64-wide), relu, dot W2 -> q = dinv * p
// Two nodes per thread; weights packed as float4 -> one LDS.128 per iter.
__global__ void __launch_bounds__(256) k_node2(const float* __restrict__ W1,
                                               const float* __restrict__ b1,
                                               const float* __restrict__ W2, int n) {
    __shared__ float4 sW4[64];         // (W1[0][j], W1[1][j], b1[j], W2[j])
    int t = threadIdx.x;
    if (t < 64) {
        sW4[t] = make_float4(W1[t], W1[64 + t], b1[t], W2[t]);
    }
    __syncthreads();
    cudaGridDependencySynchronize();   // wait for k_scatter1 (g_sab)

    int i0 = blockIdx.x * (blockDim.x * 2) + t;
    int i1 = i0 + blockDim.x;

    float dinv0 = 0.f, ca0 = 0.f, cb0 = 0.f;
    float dinv1 = 0.f, ca1 = 0.f, cb1 = 0.f;
    if (i0 < n) {
        dinv0 = g_dinv[i0];
        float2 s = g_ab[i0], a = g_sab[i0];
        ca0 = a.x + s.x; cb0 = a.y + s.y;
    }
    if (i1 < n) {
        dinv1 = g_dinv[i1];
        float2 s = g_ab[i1], a = g_sab[i1];
        ca1 = a.x + s.x; cb1 = a.y + s.y;
    }
    float p0 = 0.0f, p1 = 0.0f;
    #pragma unroll
    for (int j = 0; j < 64; j++) {
        float4 w = sW4[j];
        float h0 = fmaf(dinv0, fmaf(ca0, w.x, cb0 * w.y), w.z);
        float h1 = fmaf(dinv1, fmaf(ca1, w.x, cb1 * w.y), w.z);
        h0 = fmaxf(h0, 0.0f);
        h1 = fmaxf(h1, 0.0f);
        p0 = fmaf(h0, w.w, p0);
        p1 = fmaf(h1, w.w, p1);
    }
    if (i0 < n) g_q[i0] = dinv0 * p0;
    if (i1 < n) g_q[i1] = dinv1 * p1;
}

// K5: layer-2 edge scatter — one 32b gather + one 32b RED per edge
__global__ void __launch_bounds__(256) k_scatter2(const int4* __restrict__ row4,
                                                  const int4* __restrict__ col4, int e4) {
    int i = (blockIdx.x * blockDim.x + threadIdx.x) * 2;
    cudaGridDependencySynchronize();   // wait for k_node2 (g_q)
    #pragma unroll
    for (int u = 0; u < 2; u++) {
        int idx = i + u;
        if (idx < e4) {
            int4 r = __ldg(&row4[idx]);
            int4 c = __ldg(&col4[idx]);
            float q0 = __ldg(&g_q[r.x]);
            float q1 = __ldg(&g_q[r.y]);
            float q2 = __ldg(&g_q[r.z]);
            float q3 = __ldg(&g_q[r.w]);
            atomicAdd(&g_t[c.x], q0);
            atomicAdd(&g_t[c.y], q1);
            atomicAdd(&g_t[c.z], q2);
            atomicAdd(&g_t[c.w], q3);
        }
    }
}

// K6: final — emit output AND restore the zero-scratch invariant.
__global__ void __launch_bounds__(256) k_final(const float* __restrict__ b2,
                                               float* __restrict__ out, int n) {
    int i = blockIdx.x * blockDim.x + threadIdx.x;
    cudaGridDependencySynchronize();   // wait for k_scatter2 (g_t)
    if (i < n) {
        out[i] = fmaf(g_dinv[i], g_t[i] + g_q[i], b2[0]);
        g_deg[i] = 0.0f;
        g_sab[i] = make_float2(0.0f, 0.0f);
        g_t[i]   = 0.0f;
    }
}

template <typename F, typename... Args>
static void launch_pdl(F func, dim3 grid, dim3 block, Args... args) {
    cudaLaunchConfig_t cfg{};
    cfg.gridDim = grid;
    cfg.blockDim = block;
    cfg.dynamicSmemBytes = 0;
    cfg.stream = (cudaStream_t)0;
    cudaLaunchAttribute attr[1];
    attr[0].id = cudaLaunchAttributeProgrammaticStreamSerialization;
    attr[0].val.programmaticStreamSerializationAllowed = 1;
    cfg.attrs = attr;
    cfg.numAttrs = 1;
    cudaLaunchKernelEx(&cfg, func, args...);
}

extern "C" void kernel_launch(void* const* d_in, const int* in_sizes, int n_in,
                              void* d_out, int out_size) {
    const float* x   = (const float*)d_in[0];
    const int*   ei  = (const int*)d_in[1];
    const float* W1  = (const float*)d_in[2];
    const float* b1  = (const float*)d_in[3];
    const float* W2  = (const float*)d_in[4];
    const float* b2  = (const float*)d_in[5];
    float* out = (float*)d_out;

    const int n = NN;
    const int e4 = E4;
    const int4* row4 = (const int4*)ei;
    const int4* col4 = (const int4*)(ei + EE);

    const int TB = 256;
    const dim3 blk(TB);
    const dim3 gN((n + TB - 1) / TB);
    const dim3 gN2((n + TB * 2 - 1) / (TB * 2));
    const dim3 gE2((e4 / 2 + TB - 1) / TB);

    k_deg<<<gE2, blk>>>(col4, e4);                       // root: plain launch
    launch_pdl(k_node1,   gN,  blk, x, n);
    launch_pdl(k_scatter1, gE2, blk, row4, col4, e4);
    launch_pdl(k_node2,   gN2, blk, W1, b1, W2, n);
    launch_pdl(k_scatter2, gE2, blk, row4, col4, e4);
    launch_pdl(k_final,   gN,  blk, b2, out, n);
}

// round 11
// speedup vs baseline: 1.0098x; 1.0098x over previous
#include <cuda_runtime.h>

#define NN 100000
#define EE 3200000
#define E4 (EE / 4)

// Scratch (__device__ globals; zero-initialized at module load).
// INVARIANT: g_deg, g_sab, g_t are zero at entry to kernel_launch; k_final
// re-zeroes them after use so the invariant holds for the next call.
__device__ float  g_deg[NN];
__device__ float  g_dinv[NN];
__device__ float2 g_ab[NN];    // (dinv*x0, dinv*x1) per node
__device__ float2 g_sab[NN];   // layer-1 accumulators
__device__ float  g_q[NN];
__device__ float  g_t[NN];

__device__ __forceinline__ void red_add_v2(float2* addr, float a, float b) {
    asm volatile("red.global.add.v2.f32 [%0], {%1, %2};"
                 :: "l"(addr), "f"(a), "f"(b) : "memory");
}

// K1: degree count over edge destinations (col). 1 int4 per thread —
// short dependency chain, max resident warps for L2-latency hiding.
__global__ void __launch_bounds__(256) k_deg(const int4* __restrict__ col4, int e4) {
    int i = blockIdx.x * blockDim.x + threadIdx.x;
    if (i < e4) {
        int4 c = __ldg(&col4[i]);
        atomicAdd(&g_deg[c.x], 1.0f);
        atomicAdd(&g_deg[c.y], 1.0f);
        atomicAdd(&g_deg[c.z], 1.0f);
        atomicAdd(&g_deg[c.w], 1.0f);
    }
}

// K2: per-node dinv = rsqrt(deg + 1 self-loop); (a,b) = dinv * x
__global__ void __launch_bounds__(256) k_node1(const float* __restrict__ x, int n) {
    int i = blockIdx.x * blockDim.x + threadIdx.x;
    if (i < n) {
        float dinv = rsqrtf(g_deg[i] + 1.0f);
        float2 xi = ((const float2*)x)[i];
        g_dinv[i] = dinv;
        g_ab[i] = make_float2(dinv * xi.x, dinv * xi.y);
    }
}

// K3: layer-1 edge scatter — one 64b gather + one 64b vector RED per edge.
// 1 int4 per thread.
__global__ void __launch_bounds__(256) k_scatter1(const int4* __restrict__ row4,
                                                  const int4* __restrict__ col4, int e4) {
    int i = blockIdx.x * blockDim.x + threadIdx.x;
    if (i < e4) {
        int4 r = __ldg(&row4[i]);
        int4 c = __ldg(&col4[i]);
        float2 v0 = __ldg(&g_ab[r.x]);
        float2 v1 = __ldg(&g_ab[r.y]);
        float2 v2 = __ldg(&g_ab[r.z]);
        float2 v3 = __ldg(&g_ab[r.w]);
        red_add_v2(&g_sab[c.x], v0.x, v0.y);
        red_add_v2(&g_sab[c.y], v1.x, v1.y);
        red_add_v2(&g_sab[c.z], v2.x, v2.y);
        red_add_v2(&g_sab[c.w], v3.x, v3.y);
    }
}

// K4: per-node MLP — reconstruct h1 (64-wide), relu, dot W2 -> q = dinv * p
// Two nodes per thread; weights packed as float4 -> one LDS.128 per iter.
__global__ void __launch_bounds__(256) k_node2(const float* __restrict__ W1,
                                               const float* __restrict__ b1,
                                               const float* __restrict__ W2, int n) {
    __shared__ float4 sW4[64];         // (W1[0][j], W1[1][j], b1[j], W2[j])
    int t = threadIdx.x;
    if (t < 64) {
        sW4[t] = make_float4(W1[t], W1[64 + t], b1[t], W2[t]);
    }
    __syncthreads();

    int i0 = blockIdx.x * (blockDim.x * 2) + t;
    int i1 = i0 + blockDim.x;

    float dinv0 = 0.f, ca0 = 0.f, cb0 = 0.f;
    float dinv1 = 0.f, ca1 = 0.f, cb1 = 0.f;
    if (i0 < n) {
        dinv0 = g_dinv[i0];
        float2 s = g_ab[i0], a = g_sab[i0];
        ca0 = a.x + s.x; cb0 = a.y + s.y;
    }
    if (i1 < n) {
        dinv1 = g_dinv[i1];
        float2 s = g_ab[i1], a = g_sab[i1];
        ca1 = a.x + s.x; cb1 = a.y + s.y;
    }
    float p0 = 0.0f, p1 = 0.0f;
    #pragma unroll
    for (int j = 0; j < 64; j++) {
        float4 w = sW4[j];
        float h0 = fmaf(dinv0, fmaf(ca0, w.x, cb0 * w.y), w.z);
        float h1 = fmaf(dinv1, fmaf(ca1, w.x, cb1 * w.y), w.z);
        h0 = fmaxf(h0, 0.0f);
        h1 = fmaxf(h1, 0.0f);
        p0 = fmaf(h0, w.w, p0);
        p1 = fmaf(h1, w.w, p1);
    }
    if (i0 < n) g_q[i0] = dinv0 * p0;
    if (i1 < n) g_q[i1] = dinv1 * p1;
}

// K5: layer-2 edge scatter — one 32b gather + one 32b RED per edge.
// 1 int4 per thread.
__global__ void __launch_bounds__(256) k_scatter2(const int4* __restrict__ row4,
                                                  const int4* __restrict__ col4, int e4) {
    int i = blockIdx.x * blockDim.x + threadIdx.x;
    if (i < e4) {
        int4 r = __ldg(&row4[i]);
        int4 c = __ldg(&col4[i]);
        float q0 = __ldg(&g_q[r.x]);
        float q1 = __ldg(&g_q[r.y]);
        float q2 = __ldg(&g_q[r.z]);
        float q3 = __ldg(&g_q[r.w]);
        atomicAdd(&g_t[c.x], q0);
        atomicAdd(&g_t[c.y], q1);
        atomicAdd(&g_t[c.z], q2);
        atomicAdd(&g_t[c.w], q3);
    }
}

// K6: final — emit output AND restore the zero-scratch invariant.
__global__ void __launch_bounds__(256) k_final(const float* __restrict__ b2,
                                               float* __restrict__ out, int n) {
    int i = blockIdx.x * blockDim.x + threadIdx.x;
    if (i < n) {
        out[i] = fmaf(g_dinv[i], g_t[i] + g_q[i], b2[0]);
        g_deg[i] = 0.0f;
        g_sab[i] = make_float2(0.0f, 0.0f);
        g_t[i]   = 0.0f;
    }
}

extern "C" void kernel_launch(void* const* d_in, const int* in_sizes, int n_in,
                              void* d_out, int out_size) {
    const float* x   = (const float*)d_in[0];
    const int*   ei  = (const int*)d_in[1];
    const float* W1  = (const float*)d_in[2];
    const float* b1  = (const float*)d_in[3];
    const float* W2  = (const float*)d_in[4];
    const float* b2  = (const float*)d_in[5];
    float* out = (float*)d_out;

    const int n = NN;
    const int e4 = E4;
    const int4* row4 = (const int4*)ei;
    const int4* col4 = (const int4*)(ei + EE);

    const int TB = 256;
    const int gN  = (n + TB - 1) / TB;
    const int gN2 = (n + TB * 2 - 1) / (TB * 2);
    const int gE  = (e4 + TB - 1) / TB;        // 1 int4 per thread

    k_deg     <<<gE, TB>>>(col4, e4);
    k_node1   <<<gN, TB>>>(x, n);
    k_scatter1<<<gE, TB>>>(row4, col4, e4);
    k_node2   <<<gN2, TB>>>(W1, b1, W2, n);
    k_scatter2<<<gE, TB>>>(row4, col4, e4);
    k_final   <<<gN, TB>>>(b2, out, n);
}